// round 17
// baseline (speedup 1.0000x reference)
#include <cuda_runtime.h>
#include <cuda_fp16.h>
#include <cstdint>
#include <math.h>

#define B_ 8
#define N_ 2048
#define M_ 2048
#define D_ 256
#define KS_ 256                  // single fp16 limb
#define KC 64
#define NTILES (M_ / 128)        // 16
#define TSC (NTILES * 2)         // 32 super-chunk steps (tile, k-half)
#define THREADS 256

#define A_OFF 0
#define B_OFF 65536              // A resident: 4 chunks * 16KB
#define SMEM_BYTES (65536 + 3 * 32768)   // + 3-deep 32KB ring = 160KB

#define THR 3.0e-4f              // flag margin (~14 sigma of fp16 sim error)
#define MAXF 256

__device__ __half gA[(size_t)B_ * N_ * KS_];
__device__ __half gBt[(size_t)B_ * M_ * KS_];
__device__ float  g_inv_s[B_ * N_];
__device__ float  g_inv_d[B_ * M_];
__device__ int    g_flags[B_ * N_];
__device__ unsigned long long g_best[B_ * N_];

#define SWZ(x) ((x) ^ (((x) >> 3) & 0x70))

__device__ __forceinline__ uint32_t smem_u32(const void* p) {
    uint32_t a;
    asm("{ .reg .u64 t; cvta.to.shared.u64 t, %1; cvt.u32.u64 %0, t; }"
        : "=r"(a) : "l"(p));
    return a;
}
__device__ __forceinline__ void cp_async16(uint32_t dst, const void* src) {
    asm volatile("cp.async.cg.shared.global [%0], [%1], 16;"
                 :: "r"(dst), "l"(src) : "memory");
}
__device__ __forceinline__ void cp_commit() {
    asm volatile("cp.async.commit_group;" ::: "memory");
}
template <int N>
__device__ __forceinline__ void cp_wait() {
    asm volatile("cp.async.wait_group %0;" :: "n"(N) : "memory");
}
__device__ __forceinline__ void ldm_x4(uint32_t* r, uint32_t addr) {
    asm volatile("ldmatrix.sync.aligned.m8n8.x4.shared.b16 {%0,%1,%2,%3}, [%4];"
                 : "=r"(r[0]), "=r"(r[1]), "=r"(r[2]), "=r"(r[3]) : "r"(addr));
}
__device__ __forceinline__ void mma16816(float* d, const uint32_t* a,
                                         const uint32_t* b) {
    asm volatile(
        "mma.sync.aligned.m16n8k16.row.col.f32.f16.f16.f32 "
        "{%0,%1,%2,%3}, {%4,%5,%6,%7}, {%8,%9}, {%0,%1,%2,%3};"
        : "+f"(d[0]), "+f"(d[1]), "+f"(d[2]), "+f"(d[3])
        : "r"(a[0]), "r"(a[1]), "r"(a[2]), "r"(a[3]), "r"(b[0]), "r"(b[1]));
}

// ---------------------------------------------------------------------------
// Kernel 1: normalize rows -> one fp16 limb; store 1/norm for exact cleanup.
// ---------------------------------------------------------------------------
__global__ void prep_kernel(const float* __restrict__ src,
                            const float* __restrict__ dst) {
    int gw = (blockIdx.x * blockDim.x + threadIdx.x) >> 5;
    int lane = threadIdx.x & 31;
    if (gw >= B_ * (N_ + M_)) return;
    bool is_src = gw < B_ * N_;
    int row = is_src ? gw : gw - B_ * N_;
    const float* p = (is_src ? src : dst) + (size_t)row * D_;
    __half* o = (is_src ? gA : gBt) + (size_t)row * KS_;

    float4 v0 = ((const float4*)p)[lane * 2];
    float4 v1 = ((const float4*)p)[lane * 2 + 1];
    float x[8] = {v0.x, v0.y, v0.z, v0.w, v1.x, v1.y, v1.z, v1.w};
    float s = 0.f;
    #pragma unroll
    for (int i = 0; i < 8; i++) s = fmaf(x[i], x[i], s);
    #pragma unroll
    for (int o2 = 16; o2 > 0; o2 >>= 1) s += __shfl_xor_sync(0xffffffffu, s, o2);
    float scale = 1.0f / sqrtf(s);

    __align__(16) __half t0[8];
    #pragma unroll
    for (int i = 0; i < 8; i++) t0[i] = __float2half_rn(x[i] * scale);
    ((uint4*)o)[lane] = *(uint4*)t0;
    if (lane == 0) {
        if (is_src) g_inv_s[row] = scale;
        else        g_inv_d[row] = scale;
    }
}

// Load a 32KB B super-chunk: k-halves (kc, kc+1) of tile t into ring buf.
__device__ __forceinline__ void load_super(uint32_t sb, const __half* gBb,
                                           int t, int sc2, int buf, int tid) {
    const uint32_t dstb = sb + B_OFF + buf * 32768;
    const int kc = sc2 * 2;
    #pragma unroll
    for (int i = 0; i < 8; ++i) {
        int idx = tid + i * THREADS;
        int hs = idx >> 10;              // sub-chunk 0/1
        int rem = idx & 1023;
        int r = rem >> 3, q = rem & 7;
        const __half* src = gBb + (size_t)(t * 128 + r) * KS_ + (kc + hs) * KC;
        cp_async16(dstb + hs * 16384 + SWZ(r * 128 + q * 16),
                   (const char*)src + q * 16);
    }
}

// ---------------------------------------------------------------------------
// Kernel 2: single-limb fp16 GEMM + top-2 argmax + margin flagging.
// 8 warps (4x2), warp tile 32x64, A resident 64KB, 3-deep 32KB ring.
// ---------------------------------------------------------------------------
__global__ __launch_bounds__(THREADS, 1)
void match1_kernel(const float* __restrict__ pts, float* __restrict__ out) {
    extern __shared__ char smem[];
    const uint32_t sb = smem_u32(smem);
    const int tid = threadIdx.x;
    const int wid = tid >> 5;
    const int lane = tid & 31;
    const int b = blockIdx.y;
    const int n0 = blockIdx.x * 128;

    const int WM = (wid & 3) * 32;
    const int WN = (wid >> 2) * 64;

    const __half* gArow = gA + ((size_t)b * N_ + n0) * KS_;
    const __half* gBb   = gBt + (size_t)b * M_ * KS_;

    // prologue: A resident (4 chunks) + SC0 (group), SC1 (group)
    #pragma unroll 4
    for (int i = 0; i < 16; ++i) {
        int idx = tid + i * THREADS;
        int c = idx >> 10, rem = idx & 1023, r = rem >> 3, q = rem & 7;
        cp_async16(sb + A_OFF + c * 16384 + SWZ(r * 128 + q * 16),
                   (const char*)(gArow + (size_t)r * KS_ + c * KC) + q * 16);
    }
    load_super(sb, gBb, 0, 0, 0, tid);
    cp_commit();
    load_super(sb, gBb, 0, 1, 1, tid);
    cp_commit();

    const int ra  = (lane & 7) + ((lane >> 3) & 1) * 8;
    const int kba = (lane >> 4) * 16;
    const int nb  = (lane & 7) + ((lane >> 4) & 1) * 8;
    const int kbb = ((lane >> 3) & 1) * 16;

    float acc[2][8][4];
    #pragma unroll
    for (int f = 0; f < 2; ++f)
        #pragma unroll
        for (int nf = 0; nf < 8; ++nf)
            #pragma unroll
            for (int k = 0; k < 4; ++k) acc[f][nf][k] = 0.f;

    float b1[4] = {-1e30f, -1e30f, -1e30f, -1e30f};
    float b2[4] = {-1e30f, -1e30f, -1e30f, -1e30f};
    int   i1[4] = {0, 0, 0, 0};

    for (int SC = 0; SC < TSC; ++SC) {
        const int t = SC >> 1, sc2 = SC & 1, buf = SC % 3;
        if (SC == TSC - 1) cp_wait<0>(); else cp_wait<1>();
        __syncthreads();

        if (SC + 2 < TSC) {
            const int S2 = SC + 2;
            load_super(sb, gBb, S2 >> 1, S2 & 1, S2 % 3, tid);
            cp_commit();
        }

        #pragma unroll
        for (int sub = 0; sub < 2; ++sub) {
            const uint32_t bbase = sb + B_OFF + buf * 32768 + sub * 16384;
            const uint32_t abase = sb + A_OFF + (sc2 * 2 + sub) * 16384;
            #pragma unroll
            for (int s = 0; s < 4; ++s) {
                uint32_t bf[4][4];
                #pragma unroll
                for (int p = 0; p < 4; ++p)
                    ldm_x4(bf[p], bbase + SWZ((WN + p * 16 + nb) * 128 + s * 32 + kbb));
                uint32_t a[2][4];
                #pragma unroll
                for (int f = 0; f < 2; ++f)
                    ldm_x4(a[f], abase + SWZ((WM + f * 16 + ra) * 128 + s * 32 + kba));
                #pragma unroll
                for (int f = 0; f < 2; ++f)
                    #pragma unroll
                    for (int nf = 0; nf < 8; ++nf)
                        mma16816(acc[f][nf], a[f], &bf[nf >> 1][(nf & 1) * 2]);
            }
        }

        // tile epilogue: top-2 fold, reset acc
        if (sc2 == 1) {
            #pragma unroll
            for (int x = 0; x < 4; ++x) {
                const int f = x >> 1, hi = x & 1;
                float v1r = b1[x], v2r = b2[x]; int ir = i1[x];
                #pragma unroll
                for (int nf = 0; nf < 8; ++nf) {
                    int nbase = t * 128 + WN + nf * 8 + (lane & 3) * 2;
                    float v0 = acc[f][nf][hi * 2];
                    float v1 = acc[f][nf][hi * 2 + 1];
                    if (v0 > v1r) { v2r = v1r; v1r = v0; ir = nbase; }
                    else if (v0 > v2r) v2r = v0;
                    if (v1 > v1r) { v2r = v1r; v1r = v1; ir = nbase + 1; }
                    else if (v1 > v2r) v2r = v1;
                    acc[f][nf][hi * 2] = 0.f;
                    acc[f][nf][hi * 2 + 1] = 0.f;
                }
                b1[x] = v1r; b2[x] = v2r; i1[x] = ir;
            }
        }
    }

    // quad reduce (lanes sharing a row): merge top-2 triples
    #pragma unroll
    for (int x = 0; x < 4; ++x) {
        float v1 = b1[x], v2 = b2[x]; int ii = i1[x];
        #pragma unroll
        for (int o = 1; o <= 2; o <<= 1) {
            float w1 = __shfl_xor_sync(0xffffffffu, v1, o);
            int   j1 = __shfl_xor_sync(0xffffffffu, ii, o);
            float w2 = __shfl_xor_sync(0xffffffffu, v2, o);
            if (w1 > v1) { v2 = fmaxf(v1, w2); v1 = w1; ii = j1; }
            else         { v2 = fmaxf(v2, w1); }
        }
        b1[x] = v1; b2[x] = v2; i1[x] = ii;
    }

    // cross-warp-column combine via smem
    float* sval = (float*)smem;            // [2][128]
    int*   sidx = (int*)(smem + 1024);     // [2][128]
    float* sv2  = (float*)(smem + 2048);   // [2][128]
    __syncthreads();
    if ((lane & 3) == 0) {
        const int col = wid >> 2;
        #pragma unroll
        for (int x = 0; x < 4; ++x) {
            int row = WM + 8 * x + (lane >> 2);
            sval[col * 128 + row] = b1[x];
            sidx[col * 128 + row] = i1[x];
            sv2[col * 128 + row]  = b2[x];
        }
    }
    __syncthreads();
    if (tid < 128) {
        float v1 = sval[tid], w1 = sval[128 + tid];
        int   ia = sidx[tid], jb = sidx[128 + tid];
        float v2 = sv2[tid],  w2 = sv2[128 + tid];
        if (w1 > v1) { v2 = fmaxf(v1, w2); v1 = w1; ia = jb; }
        else         { v2 = fmaxf(v2, w1); }
        int n = n0 + tid;
        size_t row = (size_t)b * N_ + n;
        out[row * 2 + 0] = pts[((size_t)b * M_ + ia) * 2 + 0];
        out[row * 2 + 1] = pts[((size_t)b * M_ + ia) * 2 + 1];
        out[(size_t)B_ * N_ * 2 + row] = v1;
        g_flags[row] = (v1 - v2 < THR) ? 1 : 0;
        g_best[row] = 0ULL;
    }
}

// ---------------------------------------------------------------------------
// Kernel 3: exact fp32 rescan of flagged rows; packed-key atomicMax.
// grid (16 m-blocks, 8 batches), 256 threads (2 per m, d-halves).
// ---------------------------------------------------------------------------
__global__ __launch_bounds__(256, 1)
void cleanup1_kernel(const float* __restrict__ src,
                     const float* __restrict__ dst) {
    __shared__ int list[MAXF];
    __shared__ int cnt;
    __shared__ float ssrc[32][256];
    const int tid = threadIdx.x;
    const int b = blockIdx.y;

    if (tid == 0) cnt = 0;
    __syncthreads();
    for (int i = tid; i < N_; i += 256)
        if (g_flags[b * N_ + i]) {
            int k = atomicAdd(&cnt, 1);
            if (k < MAXF) list[k] = i;
        }
    __syncthreads();
    int c = min(cnt, MAXF);
    if (c == 0) return;

    const int m = blockIdx.x * 128 + (tid >> 1);
    const int half = tid & 1;
    const float inv_d = g_inv_d[b * M_ + m];
    const float* drow = dst + ((size_t)b * M_ + m) * D_ + half * 128;

    for (int g0 = 0; g0 < c; g0 += 32) {
        // load (zero-padded) flagged src rows, pre-scaled by 1/||x||
        for (int idx = tid; idx < 32 * 256; idx += 256) {
            int j = idx >> 8, d = idx & 255;
            float v = 0.f;
            if (g0 + j < c) {
                int r = list[g0 + j];
                v = src[((size_t)b * N_ + r) * D_ + d] * g_inv_s[b * N_ + r];
            }
            ssrc[j][d] = v;
        }
        __syncthreads();

        float acc[32];
        #pragma unroll
        for (int j = 0; j < 32; ++j) acc[j] = 0.f;
        #pragma unroll 4
        for (int d4 = 0; d4 < 32; ++d4) {
            float4 y = ((const float4*)drow)[d4];
            int dd = half * 128 + d4 * 4;
            #pragma unroll
            for (int j = 0; j < 32; ++j)
                acc[j] = fmaf(y.x, ssrc[j][dd],
                         fmaf(y.y, ssrc[j][dd + 1],
                         fmaf(y.z, ssrc[j][dd + 2],
                         fmaf(y.w, ssrc[j][dd + 3], acc[j]))));
        }
        #pragma unroll
        for (int j = 0; j < 32; ++j) {
            float tot = acc[j] + __shfl_xor_sync(0xffffffffu, acc[j], 1);
            if (half == 0 && g0 + j < c) {
                float sim = tot * inv_d;
                uint32_t bits = __float_as_uint(sim);
                uint32_t key32 = (bits & 0x80000000u) ? ~bits : (bits | 0x80000000u);
                unsigned long long key =
                    ((unsigned long long)key32 << 32) | (0xFFFFFFFFu - (uint32_t)m);
                atomicMax(&g_best[(size_t)b * N_ + list[g0 + j]], key);
            }
        }
        __syncthreads();
    }
}

// ---------------------------------------------------------------------------
// Kernel 4: write exact results for flagged rows.
// ---------------------------------------------------------------------------
__global__ void cleanup2_kernel(const float* __restrict__ pts,
                                float* __restrict__ out) {
    int r = blockIdx.x * 256 + threadIdx.x;
    if (r >= B_ * N_ || !g_flags[r]) return;
    unsigned long long k = g_best[r];
    uint32_t m = 0xFFFFFFFFu - (uint32_t)k;
    uint32_t kb = (uint32_t)(k >> 32);
    uint32_t bits = (kb & 0x80000000u) ? (kb ^ 0x80000000u) : ~kb;
    float conf = __uint_as_float(bits);
    int b = r >> 11;
    out[(size_t)r * 2 + 0] = pts[((size_t)b * M_ + m) * 2 + 0];
    out[(size_t)r * 2 + 1] = pts[((size_t)b * M_ + m) * 2 + 1];
    out[(size_t)B_ * N_ * 2 + r] = conf;
}

// ---------------------------------------------------------------------------
extern "C" void kernel_launch(void* const* d_in, const int* in_sizes, int n_in,
                              void* d_out, int out_size) {
    const float* desc_src   = (const float*)d_in[0];
    const float* desc_dst   = (const float*)d_in[1];
    const float* points_dst = (const float*)d_in[2];
    float* out = (float*)d_out;

    int total_rows = B_ * (N_ + M_);
    prep_kernel<<<(total_rows + 7) / 8, 256>>>(desc_src, desc_dst);

    cudaFuncSetAttribute(match1_kernel,
                         cudaFuncAttributeMaxDynamicSharedMemorySize, SMEM_BYTES);
    dim3 grid(N_ / 128, B_);
    match1_kernel<<<grid, THREADS, SMEM_BYTES>>>(points_dst, out);

    dim3 cg(16, B_);
    cleanup1_kernel<<<cg, 256>>>(desc_src, desc_dst);
    cleanup2_kernel<<<(B_ * N_) / 256, 256>>>(points_dst, out);
}